// round 1
// baseline (speedup 1.0000x reference)
#include <cuda_runtime.h>

// Problem constants: B=2, S=2048, D_MODEL=1024, H=16, Dk=64. M = B*S = 4096.

// Scratch (allocation-free rule: __device__ globals). 4 x 16 MB.
__device__ float g_q[4096 * 1024];
__device__ float g_k[4096 * 1024];
__device__ float g_v[4096 * 1024];
__device__ float g_attn[4096 * 1024];

// ---------------------------------------------------------------------------
// GEMM: C[M,N] = A[M,K] @ B[N,K]^T   (both row-major, M=4096, N=K=1024)
// Tile 128x128, BK=8, 256 threads, 8x8 microtile as 2x2 quadrants of 4x4.
// ---------------------------------------------------------------------------
__global__ __launch_bounds__(256, 2)
void gemm128(const float* __restrict__ A, const float* __restrict__ B,
             float* __restrict__ C) {
    __shared__ float As[8][132];   // [k][m], pad keeps 16B alignment, avoids conflicts
    __shared__ float Bs[8][132];   // [k][n]

    const int tid = threadIdx.x;
    const int tx = tid & 15;       // 0..15 -> n microtile
    const int ty = tid >> 4;       // 0..15 -> m microtile
    const int m0 = blockIdx.y << 7;
    const int n0 = blockIdx.x << 7;

    // loader mapping: 128 rows x 2 float4 (8 k) per matrix
    const int lr = tid >> 1;             // row in tile 0..127
    const int lc = (tid & 1) << 2;       // k offset 0 or 4
    const float* Ap = A + (size_t)(m0 + lr) * 1024 + lc;
    const float* Bp = B + (size_t)(n0 + lr) * 1024 + lc;

    float acc[2][2][4][4];
#pragma unroll
    for (int p = 0; p < 2; p++)
#pragma unroll
        for (int q = 0; q < 2; q++)
#pragma unroll
            for (int i = 0; i < 4; i++)
#pragma unroll
                for (int j = 0; j < 4; j++) acc[p][q][i][j] = 0.f;

    for (int k0 = 0; k0 < 1024; k0 += 8) {
        float4 av = *(const float4*)(Ap + k0);
        float4 bv = *(const float4*)(Bp + k0);
        __syncthreads();   // protect previous iteration's smem reads
        As[lc + 0][lr] = av.x; As[lc + 1][lr] = av.y;
        As[lc + 2][lr] = av.z; As[lc + 3][lr] = av.w;
        Bs[lc + 0][lr] = bv.x; Bs[lc + 1][lr] = bv.y;
        Bs[lc + 2][lr] = bv.z; Bs[lc + 3][lr] = bv.w;
        __syncthreads();
#pragma unroll
        for (int kk = 0; kk < 8; kk++) {
            float4 a0 = *(const float4*)&As[kk][(ty << 2)];
            float4 a1 = *(const float4*)&As[kk][(ty << 2) + 64];
            float4 b0 = *(const float4*)&Bs[kk][(tx << 2)];
            float4 b1 = *(const float4*)&Bs[kk][(tx << 2) + 64];
            float a[2][4] = {{a0.x, a0.y, a0.z, a0.w}, {a1.x, a1.y, a1.z, a1.w}};
            float b[2][4] = {{b0.x, b0.y, b0.z, b0.w}, {b1.x, b1.y, b1.z, b1.w}};
#pragma unroll
            for (int p = 0; p < 2; p++)
#pragma unroll
                for (int i = 0; i < 4; i++)
#pragma unroll
                    for (int q = 0; q < 2; q++)
#pragma unroll
                        for (int j = 0; j < 4; j++)
                            acc[p][q][i][j] += a[p][i] * b[q][j];
        }
    }

#pragma unroll
    for (int p = 0; p < 2; p++)
#pragma unroll
        for (int i = 0; i < 4; i++) {
            const int m = m0 + (p << 6) + (ty << 2) + i;
            float* Cp = C + (size_t)m * 1024 + n0 + (tx << 2);
#pragma unroll
            for (int q = 0; q < 2; q++) {
                float4 v = make_float4(acc[p][q][i][0], acc[p][q][i][1],
                                       acc[p][q][i][2], acc[p][q][i][3]);
                *(float4*)(Cp + (q << 6)) = v;
            }
        }
}

// ---------------------------------------------------------------------------
// Flash attention (fp32): one CTA = 64 query rows for one (b,h).
// q/k/v live in [B,S,1024] layout (head h at column h*64). Online softmax.
// Shared: Qt[64][68] (d-major, pre-scaled), Kt[64][68] (d-major),
//         Ps[64][68] (i-major), Vs[64][64] (j-major). Total 68608 B dynamic.
// ---------------------------------------------------------------------------
__global__ __launch_bounds__(256)
void attn64(const float* __restrict__ gq, const float* __restrict__ gk,
            const float* __restrict__ gv, float* __restrict__ go) {
    extern __shared__ float sm[];
    float* Qt = sm;                // [64][68]  Qt[d][i]
    float* Kt = sm + 64 * 68;      // [64][68]  Kt[d][j]
    float* Ps = sm + 2 * 64 * 68;  // [64][68]  Ps[i][j]
    float* Vs = sm + 3 * 64 * 68;  // [64][64]  Vs[j][d]

    const int tid = threadIdx.x;
    const int tx = tid & 15;   // key/dv microtile
    const int ty = tid >> 4;   // query microtile
    const int b = blockIdx.y >> 4;
    const int h = blockIdx.y & 15;
    const int q0 = blockIdx.x << 6;

    const float* qb = gq + ((size_t)(b * 2048 + q0)) * 1024 + h * 64;
    const float* kb = gk + ((size_t)(b * 2048)) * 1024 + h * 64;
    const float* vb = gv + ((size_t)(b * 2048)) * 1024 + h * 64;

    // load Q tile transposed + fold 1/sqrt(Dk)=0.125
#pragma unroll
    for (int l = 0; l < 4; l++) {
        int idx = tid + (l << 8);
        int r = idx >> 4;
        int c = (idx & 15) << 2;
        float4 v = *(const float4*)(qb + (size_t)r * 1024 + c);
        Qt[(c + 0) * 68 + r] = v.x * 0.125f;
        Qt[(c + 1) * 68 + r] = v.y * 0.125f;
        Qt[(c + 2) * 68 + r] = v.z * 0.125f;
        Qt[(c + 3) * 68 + r] = v.w * 0.125f;
    }

    float mrow[4], lrow[4], acc[4][4];
#pragma unroll
    for (int i = 0; i < 4; i++) {
        mrow[i] = -1e30f;
        lrow[i] = 0.f;
#pragma unroll
        for (int j = 0; j < 4; j++) acc[i][j] = 0.f;
    }
    __syncthreads();

    for (int s0 = 0; s0 < 2048; s0 += 64) {
        // load K (transposed) and V (natural) tiles
#pragma unroll
        for (int l = 0; l < 4; l++) {
            int idx = tid + (l << 8);
            int r = idx >> 4;
            int c = (idx & 15) << 2;
            float4 kv = *(const float4*)(kb + (size_t)(s0 + r) * 1024 + c);
            float4 vv = *(const float4*)(vb + (size_t)(s0 + r) * 1024 + c);
            Kt[(c + 0) * 68 + r] = kv.x;
            Kt[(c + 1) * 68 + r] = kv.y;
            Kt[(c + 2) * 68 + r] = kv.z;
            Kt[(c + 3) * 68 + r] = kv.w;
            *(float4*)&Vs[(r << 6) + c] = vv;
        }
        __syncthreads();

        // scores: s[i][j] = sum_d Qt[d][i0+i] * Kt[d][j0+j]
        float s[4][4];
#pragma unroll
        for (int i = 0; i < 4; i++)
#pragma unroll
            for (int j = 0; j < 4; j++) s[i][j] = 0.f;
#pragma unroll 4
        for (int d = 0; d < 64; d++) {
            float4 a = *(const float4*)&Qt[d * 68 + (ty << 2)];
            float4 k4 = *(const float4*)&Kt[d * 68 + (tx << 2)];
            float av[4] = {a.x, a.y, a.z, a.w};
            float kv[4] = {k4.x, k4.y, k4.z, k4.w};
#pragma unroll
            for (int i = 0; i < 4; i++)
#pragma unroll
                for (int j = 0; j < 4; j++) s[i][j] += av[i] * kv[j];
        }

        // online softmax update (row groups = 16 lanes sharing ty)
#pragma unroll
        for (int i = 0; i < 4; i++) {
            float mx = fmaxf(fmaxf(s[i][0], s[i][1]), fmaxf(s[i][2], s[i][3]));
            mx = fmaxf(mx, __shfl_xor_sync(0xffffffffu, mx, 1));
            mx = fmaxf(mx, __shfl_xor_sync(0xffffffffu, mx, 2));
            mx = fmaxf(mx, __shfl_xor_sync(0xffffffffu, mx, 4));
            mx = fmaxf(mx, __shfl_xor_sync(0xffffffffu, mx, 8));
            float mn = fmaxf(mrow[i], mx);
            float alpha = __expf(mrow[i] - mn);
            mrow[i] = mn;
            float rs = 0.f;
#pragma unroll
            for (int j = 0; j < 4; j++) {
                s[i][j] = __expf(s[i][j] - mn);
                rs += s[i][j];
            }
            rs += __shfl_xor_sync(0xffffffffu, rs, 1);
            rs += __shfl_xor_sync(0xffffffffu, rs, 2);
            rs += __shfl_xor_sync(0xffffffffu, rs, 4);
            rs += __shfl_xor_sync(0xffffffffu, rs, 8);
            lrow[i] = lrow[i] * alpha + rs;
#pragma unroll
            for (int j = 0; j < 4; j++) acc[i][j] *= alpha;
        }

        // publish P
#pragma unroll
        for (int i = 0; i < 4; i++)
#pragma unroll
            for (int j = 0; j < 4; j++)
                Ps[((ty << 2) + i) * 68 + (tx << 2) + j] = s[i][j];
        __syncthreads();

        // O += P @ V : acc[i][dd] += sum_j Ps[i0+i][j] * Vs[j][d0+dd]
#pragma unroll 4
        for (int j = 0; j < 64; j++) {
            float4 vv = *(const float4*)&Vs[(j << 6) + (tx << 2)];
            float p0 = Ps[((ty << 2) + 0) * 68 + j];
            float p1 = Ps[((ty << 2) + 1) * 68 + j];
            float p2 = Ps[((ty << 2) + 2) * 68 + j];
            float p3 = Ps[((ty << 2) + 3) * 68 + j];
            acc[0][0] += p0 * vv.x; acc[0][1] += p0 * vv.y;
            acc[0][2] += p0 * vv.z; acc[0][3] += p0 * vv.w;
            acc[1][0] += p1 * vv.x; acc[1][1] += p1 * vv.y;
            acc[1][2] += p1 * vv.z; acc[1][3] += p1 * vv.w;
            acc[2][0] += p2 * vv.x; acc[2][1] += p2 * vv.y;
            acc[2][2] += p2 * vv.z; acc[2][3] += p2 * vv.w;
            acc[3][0] += p3 * vv.x; acc[3][1] += p3 * vv.y;
            acc[3][2] += p3 * vv.z; acc[3][3] += p3 * vv.w;
        }
        __syncthreads();
    }

    // normalize + store into [B,S,H*Dk] layout
    float* ob = go + ((size_t)(b * 2048 + q0)) * 1024 + h * 64;
#pragma unroll
    for (int i = 0; i < 4; i++) {
        float inv = 1.0f / lrow[i];
        float4 v = make_float4(acc[i][0] * inv, acc[i][1] * inv,
                               acc[i][2] * inv, acc[i][3] * inv);
        *(float4*)(ob + (size_t)((ty << 2) + i) * 1024 + (tx << 2)) = v;
    }
}

// ---------------------------------------------------------------------------
// Launch
// ---------------------------------------------------------------------------
extern "C" void kernel_launch(void* const* d_in, const int* in_sizes, int n_in,
                              void* d_out, int out_size) {
    const float* Q  = (const float*)d_in[0];
    const float* K  = (const float*)d_in[1];
    const float* V  = (const float*)d_in[2];
    const float* Wq = (const float*)d_in[3];
    const float* Wk = (const float*)d_in[4];
    const float* Wv = (const float*)d_in[5];
    const float* Wo = (const float*)d_in[6];
    float* out = (float*)d_out;

    float *q, *k, *v, *a;
    cudaGetSymbolAddress((void**)&q, g_q);
    cudaGetSymbolAddress((void**)&k, g_k);
    cudaGetSymbolAddress((void**)&v, g_v);
    cudaGetSymbolAddress((void**)&a, g_attn);

    const int SMEM_ATTN = (3 * 64 * 68 + 64 * 64) * 4;  // 68608 B
    cudaFuncSetAttribute(attn64, cudaFuncAttributeMaxDynamicSharedMemorySize,
                         SMEM_ATTN);

    dim3 gg(8, 32);    // N/128, M/128
    gemm128<<<gg, 256>>>(Q, Wq, q);
    gemm128<<<gg, 256>>>(K, Wk, k);
    gemm128<<<gg, 256>>>(V, Wv, v);

    dim3 ag(32, 32);   // S/64 query blocks, B*H
    attn64<<<ag, 256, SMEM_ATTN>>>(q, k, v, a);

    gemm128<<<gg, 256>>>(a, Wo, out);
}

// round 2
// speedup vs baseline: 1.1117x; 1.1117x over previous
#include <cuda_runtime.h>

// B=2, S=2048, D_MODEL=1024, H=16, Dk=64. M = B*S = 4096.

typedef unsigned long long u64;

__device__ float g_q[4096 * 1024];
__device__ float g_k[4096 * 1024];
__device__ float g_v[4096 * 1024];
__device__ float g_attn[4096 * 1024];

// ---- packed f32x2 helpers (exact fp32 numerics, 2 FMAs/instr) ----
__device__ __forceinline__ u64 pack2(float x, float y) {
    u64 r; asm("mov.b64 %0, {%1, %2};" : "=l"(r) : "f"(x), "f"(y)); return r;
}
__device__ __forceinline__ u64 dup2(float x) { return pack2(x, x); }
__device__ __forceinline__ void unpack2(u64 v, float& x, float& y) {
    asm("mov.b64 {%0, %1}, %2;" : "=f"(x), "=f"(y) : "l"(v));
}
__device__ __forceinline__ u64 ffma2(u64 c, u64 a, u64 b) {
    u64 d; asm("fma.rn.f32x2 %0, %1, %2, %3;" : "=l"(d) : "l"(a), "l"(b), "l"(c));
    return d;
}
__device__ __forceinline__ u64 fmul2(u64 a, u64 b) {
    u64 d; asm("mul.rn.f32x2 %0, %1, %2;" : "=l"(d) : "l"(a), "l"(b));
    return d;
}

// ---------------------------------------------------------------------------
// GEMM: C[M,N] = A[M,K] @ B[N,K]^T (row-major, M=4096, N=K=1024)
// 128x128 tile, BK=8, 256 threads, 8x8 microtile, f32x2 inner loop.
// ---------------------------------------------------------------------------
__global__ __launch_bounds__(256, 2)
void gemm128(const float* __restrict__ A, const float* __restrict__ B,
             float* __restrict__ C) {
    __shared__ float As[8][132];
    __shared__ float Bs[8][132];

    const int tid = threadIdx.x;
    const int tx = tid & 15;
    const int ty = tid >> 4;
    const int m0 = blockIdx.y << 7;
    const int n0 = blockIdx.x << 7;

    const int lr = tid >> 1;
    const int lc = (tid & 1) << 2;
    const float* Ap = A + (size_t)(m0 + lr) * 1024 + lc;
    const float* Bp = B + (size_t)(n0 + lr) * 1024 + lc;

    u64 acc[2][2][2][4];  // [mq][nq][m-pair][n] ; each u64 = 2 m-rows
#pragma unroll
    for (int p = 0; p < 2; p++)
#pragma unroll
        for (int q = 0; q < 2; q++)
#pragma unroll
            for (int pi = 0; pi < 2; pi++)
#pragma unroll
                for (int j = 0; j < 4; j++) acc[p][q][pi][j] = 0ull;

    for (int k0 = 0; k0 < 1024; k0 += 8) {
        float4 av = *(const float4*)(Ap + k0);
        float4 bv = *(const float4*)(Bp + k0);
        __syncthreads();
        As[lc + 0][lr] = av.x; As[lc + 1][lr] = av.y;
        As[lc + 2][lr] = av.z; As[lc + 3][lr] = av.w;
        Bs[lc + 0][lr] = bv.x; Bs[lc + 1][lr] = bv.y;
        Bs[lc + 2][lr] = bv.z; Bs[lc + 3][lr] = bv.w;
        __syncthreads();
#pragma unroll
        for (int kk = 0; kk < 8; kk++) {
            ulonglong2 a0 = *(const ulonglong2*)&As[kk][(ty << 2)];
            ulonglong2 a1 = *(const ulonglong2*)&As[kk][(ty << 2) + 64];
            float4 b0 = *(const float4*)&Bs[kk][(tx << 2)];
            float4 b1 = *(const float4*)&Bs[kk][(tx << 2) + 64];
            u64 ap2[2][2] = {{a0.x, a0.y}, {a1.x, a1.y}};
            u64 bd[2][4] = {{dup2(b0.x), dup2(b0.y), dup2(b0.z), dup2(b0.w)},
                            {dup2(b1.x), dup2(b1.y), dup2(b1.z), dup2(b1.w)}};
#pragma unroll
            for (int p = 0; p < 2; p++)
#pragma unroll
                for (int pi = 0; pi < 2; pi++)
#pragma unroll
                    for (int q = 0; q < 2; q++)
#pragma unroll
                        for (int j = 0; j < 4; j++)
                            acc[p][q][pi][j] =
                                ffma2(acc[p][q][pi][j], ap2[p][pi], bd[q][j]);
        }
    }

#pragma unroll
    for (int p = 0; p < 2; p++)
#pragma unroll
        for (int pi = 0; pi < 2; pi++) {
            float lo[2][4], hi[2][4];
#pragma unroll
            for (int q = 0; q < 2; q++)
#pragma unroll
                for (int j = 0; j < 4; j++)
                    unpack2(acc[p][q][pi][j], lo[q][j], hi[q][j]);
            const int m = m0 + (p << 6) + (ty << 2) + (pi << 1);
            float* Cp = C + (size_t)m * 1024 + n0 + (tx << 2);
#pragma unroll
            for (int q = 0; q < 2; q++) {
                *(float4*)(Cp + (q << 6)) =
                    make_float4(lo[q][0], lo[q][1], lo[q][2], lo[q][3]);
                *(float4*)(Cp + 1024 + (q << 6)) =
                    make_float4(hi[q][0], hi[q][1], hi[q][2], hi[q][3]);
            }
        }
}

// ---------------------------------------------------------------------------
// Flash attention fp32 + f32x2: CTA = 128 queries x (64-key tiles), one (b,h).
// 256 threads; score microtile 8q x 4k (pairs along q); PV 8q x 4d (pairs
// along d). P tile is warp-local (row group = 16 lanes of one warp).
// Smem: Qt[64][132] d-major, Kt[64][68] d-major, Vs[64][68], Ps[128][68].
// ---------------------------------------------------------------------------
__global__ __launch_bounds__(256, 2)
void attn128(const float* __restrict__ gq, const float* __restrict__ gk,
             const float* __restrict__ gv, float* __restrict__ go) {
    extern __shared__ float sm[];
    float* Qt = sm;                       // [64][132]   Qt[d][q]
    float* Kt = sm + 64 * 132;            // [64][68]    Kt[d][k]
    float* Vs = Kt + 64 * 68;             // [64][68]    Vs[k][d]
    float* Ps = Vs + 64 * 68;             // [128][68]   Ps[q][k]

    const int tid = threadIdx.x;
    const int tx = tid & 15;              // k / d microtile (x4)
    const int ty = tid >> 4;              // q microtile (x8)
    const int b = blockIdx.y >> 4;
    const int h = blockIdx.y & 15;
    const int q0 = blockIdx.x << 7;

    const float* qb = gq + ((size_t)(b * 2048 + q0)) * 1024 + h * 64;
    const float* kb = gk + ((size_t)(b * 2048)) * 1024 + h * 64;
    const float* vb = gv + ((size_t)(b * 2048)) * 1024 + h * 64;

    // Q tile transposed + scale 1/8
#pragma unroll
    for (int l = 0; l < 8; l++) {
        int r = (l << 4) + ty;
        int c = tx << 2;
        float4 v = *(const float4*)(qb + (size_t)r * 1024 + c);
        Qt[(c + 0) * 132 + r] = v.x * 0.125f;
        Qt[(c + 1) * 132 + r] = v.y * 0.125f;
        Qt[(c + 2) * 132 + r] = v.z * 0.125f;
        Qt[(c + 3) * 132 + r] = v.w * 0.125f;
    }

    float mrow[8], lrow[8];
    u64 ap[8][2];                          // O acc: 8 q-rows x (2 d-pairs)
#pragma unroll
    for (int i = 0; i < 8; i++) {
        mrow[i] = -1e30f; lrow[i] = 0.f;
        ap[i][0] = 0ull; ap[i][1] = 0ull;
    }
    __syncthreads();

    for (int s0 = 0; s0 < 2048; s0 += 64) {
        // stage K/V tile in regs, then commit to smem
        float4 kr[4], vr[4];
#pragma unroll
        for (int l = 0; l < 4; l++) {
            int r = (l << 4) + ty;
            int c = tx << 2;
            kr[l] = *(const float4*)(kb + (size_t)(s0 + r) * 1024 + c);
            vr[l] = *(const float4*)(vb + (size_t)(s0 + r) * 1024 + c);
        }
        __syncthreads();
#pragma unroll
        for (int l = 0; l < 4; l++) {
            int r = (l << 4) + ty;
            int c = tx << 2;
            Kt[(c + 0) * 68 + r] = kr[l].x;
            Kt[(c + 1) * 68 + r] = kr[l].y;
            Kt[(c + 2) * 68 + r] = kr[l].z;
            Kt[(c + 3) * 68 + r] = kr[l].w;
            *(float4*)&Vs[r * 68 + c] = vr[l];
        }
        __syncthreads();

        // scores: 8q x 4k per thread, pairs along q
        u64 sp[4][4];
#pragma unroll
        for (int qi = 0; qi < 4; qi++)
#pragma unroll
            for (int j = 0; j < 4; j++) sp[qi][j] = 0ull;
#pragma unroll 8
        for (int d = 0; d < 64; d++) {
            ulonglong2 qa = *(const ulonglong2*)&Qt[d * 132 + (ty << 3)];
            ulonglong2 qc = *(const ulonglong2*)&Qt[d * 132 + (ty << 3) + 4];
            float4 kf = *(const float4*)&Kt[d * 68 + (tx << 2)];
            u64 qp[4] = {qa.x, qa.y, qc.x, qc.y};
            u64 kd[4] = {dup2(kf.x), dup2(kf.y), dup2(kf.z), dup2(kf.w)};
#pragma unroll
            for (int qi = 0; qi < 4; qi++)
#pragma unroll
                for (int j = 0; j < 4; j++)
                    sp[qi][j] = ffma2(sp[qi][j], qp[qi], kd[j]);
        }

        // unpack to scalar rows
        float s[8][4];
#pragma unroll
        for (int qi = 0; qi < 4; qi++)
#pragma unroll
            for (int j = 0; j < 4; j++)
                unpack2(sp[qi][j], s[2 * qi][j], s[2 * qi + 1][j]);

        // online softmax per row (16 tx lanes share a row group)
#pragma unroll
        for (int i = 0; i < 8; i++) {
            float mx = fmaxf(fmaxf(s[i][0], s[i][1]), fmaxf(s[i][2], s[i][3]));
            mx = fmaxf(mx, __shfl_xor_sync(0xffffffffu, mx, 1));
            mx = fmaxf(mx, __shfl_xor_sync(0xffffffffu, mx, 2));
            mx = fmaxf(mx, __shfl_xor_sync(0xffffffffu, mx, 4));
            mx = fmaxf(mx, __shfl_xor_sync(0xffffffffu, mx, 8));
            float mn = fmaxf(mrow[i], mx);
            float alpha = __expf(mrow[i] - mn);
            mrow[i] = mn;
            float rs = 0.f;
#pragma unroll
            for (int j = 0; j < 4; j++) {
                s[i][j] = __expf(s[i][j] - mn);
                rs += s[i][j];
            }
            rs += __shfl_xor_sync(0xffffffffu, rs, 1);
            rs += __shfl_xor_sync(0xffffffffu, rs, 2);
            rs += __shfl_xor_sync(0xffffffffu, rs, 4);
            rs += __shfl_xor_sync(0xffffffffu, rs, 8);
            lrow[i] = lrow[i] * alpha + rs;
            u64 ad = dup2(alpha);
            ap[i][0] = fmul2(ap[i][0], ad);
            ap[i][1] = fmul2(ap[i][1], ad);
        }

        // publish P (warp-local: row group lives in one warp)
#pragma unroll
        for (int i = 0; i < 8; i++)
            *(float4*)&Ps[((ty << 3) + i) * 68 + (tx << 2)] =
                make_float4(s[i][0], s[i][1], s[i][2], s[i][3]);
        __syncwarp();

        // O += P @ V : pairs along d, dup p
#pragma unroll 2
        for (int j0 = 0; j0 < 64; j0 += 4) {
            float4 pr[8];
#pragma unroll
            for (int i = 0; i < 8; i++)
                pr[i] = *(const float4*)&Ps[((ty << 3) + i) * 68 + j0];
            u64 vp[4][2];
#pragma unroll
            for (int jj = 0; jj < 4; jj++) {
                ulonglong2 vv =
                    *(const ulonglong2*)&Vs[(j0 + jj) * 68 + (tx << 2)];
                vp[jj][0] = vv.x; vp[jj][1] = vv.y;
            }
#pragma unroll
            for (int i = 0; i < 8; i++) {
                const float* pf = &pr[i].x;
#pragma unroll
                for (int jj = 0; jj < 4; jj++) {
                    u64 pd = dup2(pf[jj]);
                    ap[i][0] = ffma2(ap[i][0], pd, vp[jj][0]);
                    ap[i][1] = ffma2(ap[i][1], pd, vp[jj][1]);
                }
            }
        }
    }

    // normalize + store
    float* ob = go + ((size_t)(b * 2048 + q0)) * 1024 + h * 64;
#pragma unroll
    for (int i = 0; i < 8; i++) {
        float inv = 1.0f / lrow[i];
        float o0, o1, o2, o3;
        unpack2(ap[i][0], o0, o1);
        unpack2(ap[i][1], o2, o3);
        *(float4*)(ob + (size_t)((ty << 3) + i) * 1024 + (tx << 2)) =
            make_float4(o0 * inv, o1 * inv, o2 * inv, o3 * inv);
    }
}

// ---------------------------------------------------------------------------
extern "C" void kernel_launch(void* const* d_in, const int* in_sizes, int n_in,
                              void* d_out, int out_size) {
    const float* Q  = (const float*)d_in[0];
    const float* K  = (const float*)d_in[1];
    const float* V  = (const float*)d_in[2];
    const float* Wq = (const float*)d_in[3];
    const float* Wk = (const float*)d_in[4];
    const float* Wv = (const float*)d_in[5];
    const float* Wo = (const float*)d_in[6];
    float* out = (float*)d_out;

    float *q, *k, *v, *a;
    cudaGetSymbolAddress((void**)&q, g_q);
    cudaGetSymbolAddress((void**)&k, g_k);
    cudaGetSymbolAddress((void**)&v, g_v);
    cudaGetSymbolAddress((void**)&a, g_attn);

    const int SMEM_ATTN = (64 * 132 + 64 * 68 + 64 * 68 + 128 * 68) * 4; // 103424
    cudaFuncSetAttribute(attn128, cudaFuncAttributeMaxDynamicSharedMemorySize,
                         SMEM_ATTN);

    dim3 gg(8, 32);    // N/128, M/128
    gemm128<<<gg, 256>>>(Q, Wq, q);
    gemm128<<<gg, 256>>>(K, Wk, k);
    gemm128<<<gg, 256>>>(V, Wv, v);

    dim3 ag(16, 32);   // S/128 query blocks, B*H
    attn128<<<ag, 256, SMEM_ATTN>>>(q, k, v, a);

    gemm128<<<gg, 256>>>(a, Wo, out);
}

// round 4
// speedup vs baseline: 1.6441x; 1.4789x over previous
#include <cuda_runtime.h>
#include <cuda_bf16.h>
#include <cstdint>

typedef unsigned long long u64;

// Scratch (__device__ globals; no allocs allowed)
__device__ float g_q[4096 * 1024];
__device__ float g_k[4096 * 1024];
__device__ float g_v[4096 * 1024];
__device__ float g_attn[4096 * 1024];
__device__ __nv_bfloat16 g_ah[4096 * 1024];
__device__ __nv_bfloat16 g_al[4096 * 1024];
__device__ __nv_bfloat16 g_wh[1024 * 1024];
__device__ __nv_bfloat16 g_wl[1024 * 1024];

// ---------------- packed f32x2 helpers ----------------
__device__ __forceinline__ u64 pack2(float x, float y) {
    u64 r; asm("mov.b64 %0, {%1, %2};" : "=l"(r) : "f"(x), "f"(y)); return r;
}
__device__ __forceinline__ u64 dup2(float x) { return pack2(x, x); }
__device__ __forceinline__ void unpack2(u64 v, float& x, float& y) {
    asm("mov.b64 {%0, %1}, %2;" : "=f"(x), "=f"(y) : "l"(v));
}
__device__ __forceinline__ u64 ffma2(u64 c, u64 a, u64 b) {
    u64 d; asm("fma.rn.f32x2 %0, %1, %2, %3;" : "=l"(d) : "l"(a), "l"(b), "l"(c));
    return d;
}
__device__ __forceinline__ u64 fmul2(u64 a, u64 b) {
    u64 d; asm("mul.rn.f32x2 %0, %1, %2;" : "=l"(d) : "l"(a), "l"(b));
    return d;
}

// ---------------- mma.sync / ldmatrix / cp.async helpers ----------------
__device__ __forceinline__ uint32_t smem_u32(const void* p) {
    uint32_t a;
    asm("{ .reg .u64 t; cvta.to.shared.u64 t, %1; cvt.u32.u64 %0, t; }"
        : "=r"(a) : "l"(p));
    return a;
}
__device__ __forceinline__ void cp_async16(uint32_t s, const void* g) {
    asm volatile("cp.async.cg.shared.global [%0], [%1], 16;" :: "r"(s), "l"(g));
}
__device__ __forceinline__ void cp_commit() {
    asm volatile("cp.async.commit_group;" ::: "memory");
}
template <int N>
__device__ __forceinline__ void cp_wait() {
    asm volatile("cp.async.wait_group %0;" :: "n"(N) : "memory");
}
__device__ __forceinline__ void ldsm4(uint32_t* r, uint32_t a) {
    asm volatile("ldmatrix.sync.aligned.m8n8.x4.shared.b16 {%0,%1,%2,%3}, [%4];"
                 : "=r"(r[0]), "=r"(r[1]), "=r"(r[2]), "=r"(r[3]) : "r"(a));
}
__device__ __forceinline__ void mma_bf16(float* c, const uint32_t* a,
                                         const uint32_t* b) {
    asm volatile(
        "mma.sync.aligned.m16n8k16.row.col.f32.bf16.bf16.f32 "
        "{%0,%1,%2,%3}, {%4,%5,%6,%7}, {%8,%9}, {%0,%1,%2,%3};"
        : "+f"(c[0]), "+f"(c[1]), "+f"(c[2]), "+f"(c[3])
        : "r"(a[0]), "r"(a[1]), "r"(a[2]), "r"(a[3]), "r"(b[0]), "r"(b[1]));
}

// ---------------------------------------------------------------------------
// fp32 -> (bf16 hi, bf16 lo) split conversion
// ---------------------------------------------------------------------------
__global__ void cvt_bf16x2(const float* __restrict__ x,
                           __nv_bfloat16* __restrict__ hi,
                           __nv_bfloat16* __restrict__ lo, int n4) {
    int i = blockIdx.x * blockDim.x + threadIdx.x;
    if (i >= n4) return;
    float4 v = ((const float4*)x)[i];
    __nv_bfloat16 h0 = __float2bfloat16(v.x);
    __nv_bfloat16 h1 = __float2bfloat16(v.y);
    __nv_bfloat16 h2 = __float2bfloat16(v.z);
    __nv_bfloat16 h3 = __float2bfloat16(v.w);
    __nv_bfloat16 l0 = __float2bfloat16(v.x - __bfloat162float(h0));
    __nv_bfloat16 l1 = __float2bfloat16(v.y - __bfloat162float(h1));
    __nv_bfloat16 l2 = __float2bfloat16(v.z - __bfloat162float(h2));
    __nv_bfloat16 l3 = __float2bfloat16(v.w - __bfloat162float(h3));
    ((__nv_bfloat162*)hi)[2 * i]     = __nv_bfloat162(h0, h1);
    ((__nv_bfloat162*)hi)[2 * i + 1] = __nv_bfloat162(h2, h3);
    ((__nv_bfloat162*)lo)[2 * i]     = __nv_bfloat162(l0, l1);
    ((__nv_bfloat162*)lo)[2 * i + 1] = __nv_bfloat162(l2, l3);
}

// ---------------------------------------------------------------------------
// Tensor-core GEMM via mma.sync bf16 3-term split:
// C[4096,1024] = (Ah+Al) @ (Bh+Bl)^T, dropping Al*Bl.
// CTA 128x128, 8 warps (4m x 2n -> 32x64 warp tile), BK=64, cp.async
// double-buffered smem, XOR-swizzled for conflict-free ldmatrix.
// ---------------------------------------------------------------------------
__global__ __launch_bounds__(256, 1)
void gemm_mma(const __nv_bfloat16* __restrict__ Ah,
              const __nv_bfloat16* __restrict__ Al,
              const __nv_bfloat16* __restrict__ Bh,
              const __nv_bfloat16* __restrict__ Bl,
              float* __restrict__ C) {
    extern __shared__ char smem[];
    const uint32_t sb = smem_u32(smem);

    const int tid = threadIdx.x;
    const int wid = tid >> 5, lid = tid & 31;
    const int m0 = blockIdx.y << 7, n0 = blockIdx.x << 7;
    const int wm = (wid & 3) << 5;     // warp m offset within tile (0..96)
    const int wn = (wid >> 2) << 6;    // warp n offset within tile (0 or 64)

    // --- cp.async per-thread mapping: chunk = (row, c8) of a 128x64bf16 tile
    const int lrow = tid >> 3;         // 0..31 (4 passes of 32 rows)
    const int lc8 = tid & 7;           // 16B chunk within 128B row
    const uint32_t soff0 = (uint32_t)(lrow * 128 + ((lc8 ^ (lrow & 7)) << 4));
    const __nv_bfloat16* gsrc[4] = {Ah, Al, Bh, Bl};
    const int grb[4] = {m0, m0, n0, n0};

    // --- ldmatrix per-lane row precompute
    const int grp = lid >> 3, win = lid & 7;
    // A frag rows: matrices (m-half, k-half) = (grp&1, grp>>1)
    int rowA[2], aswA[2]; uint32_t abase[2];
    const int gkA = grp >> 1;
#pragma unroll
    for (int i = 0; i < 2; i++) {
        rowA[i] = wm + i * 16 + ((grp & 1) << 3) + win;
        abase[i] = (uint32_t)(rowA[i] * 128);
        aswA[i] = rowA[i] & 7;
    }
    // B frag rows: matrices (k-half, n-half) = (grp&1, grp>>1)
    int aswB[4]; uint32_t bbase[4];
    const int gkB = grp & 1;
#pragma unroll
    for (int j = 0; j < 4; j++) {
        int r = wn + j * 16 + ((grp >> 1) << 3) + win;
        bbase[j] = (uint32_t)(r * 128);
        aswB[j] = r & 7;
    }

    float acc[2][8][4];
#pragma unroll
    for (int i = 0; i < 2; i++)
#pragma unroll
        for (int jt = 0; jt < 8; jt++)
#pragma unroll
            for (int e = 0; e < 4; e++) acc[i][jt][e] = 0.f;

    // stage loader: 4 tiles x 4 passes of cp.async 16B
    auto load_stage = [&](int st, int kb) {
        const uint32_t stb = sb + (uint32_t)st * 65536u;
#pragma unroll
        for (int t = 0; t < 4; t++) {
#pragma unroll
            for (int i = 0; i < 4; i++) {
                int row = lrow + (i << 5);
                const __nv_bfloat16* g =
                    gsrc[t] + (size_t)(grb[t] + row) * 1024 + kb * 64 + lc8 * 8;
                cp_async16(stb + (uint32_t)t * 16384u + soff0 + (uint32_t)(i << 12), g);
            }
        }
    };

    load_stage(0, 0);
    cp_commit();

    for (int kb = 0; kb < 16; kb++) {
        const int st = kb & 1;
        if (kb < 15) {
            load_stage(st ^ 1, kb + 1);
            cp_commit();
            cp_wait<1>();
        } else {
            cp_wait<0>();
        }
        __syncthreads();

        const uint32_t stb = sb + (uint32_t)st * 65536u;
#pragma unroll
        for (int t = 0; t < 4; t++) {
            uint32_t afh[2][4], afl[2][4];
#pragma unroll
            for (int i = 0; i < 2; i++) {
                uint32_t off = abase[i] + (uint32_t)((((2 * t + gkA) ^ aswA[i]) << 4));
                ldsm4(afh[i], stb + off);
                ldsm4(afl[i], stb + 16384u + off);
            }
            uint32_t bfh[4][4], bfl[4][4];
#pragma unroll
            for (int j = 0; j < 4; j++) {
                uint32_t off = bbase[j] + (uint32_t)((((2 * t + gkB) ^ aswB[j]) << 4));
                ldsm4(bfh[j], stb + 32768u + off);
                ldsm4(bfl[j], stb + 49152u + off);
            }
#pragma unroll
            for (int i = 0; i < 2; i++)
#pragma unroll
                for (int jt = 0; jt < 8; jt++) {
                    const int j = jt >> 1, hf = (jt & 1) << 1;
                    mma_bf16(acc[i][jt], afh[i], &bfh[j][hf]);
                    mma_bf16(acc[i][jt], afh[i], &bfl[j][hf]);
                    mma_bf16(acc[i][jt], afl[i], &bfh[j][hf]);
                }
        }
        __syncthreads();
    }

    // epilogue: c0,c1 -> C[g][2c..], c2,c3 -> C[g+8][2c..]
    const int eg = lid >> 2, ec = lid & 3;
#pragma unroll
    for (int i = 0; i < 2; i++) {
        const int row = m0 + wm + i * 16 + eg;
#pragma unroll
        for (int jt = 0; jt < 8; jt++) {
            const int col = n0 + wn + jt * 8 + ec * 2;
            *(float2*)(C + (size_t)row * 1024 + col) =
                make_float2(acc[i][jt][0], acc[i][jt][1]);
            *(float2*)(C + (size_t)(row + 8) * 1024 + col) =
                make_float2(acc[i][jt][2], acc[i][jt][3]);
        }
    }
}

// ---------------------------------------------------------------------------
// Flash attention fp32 + f32x2 (unchanged, proven at 854 us)
// ---------------------------------------------------------------------------
__global__ __launch_bounds__(256, 2)
void attn128(const float* __restrict__ gq, const float* __restrict__ gk,
             const float* __restrict__ gv, float* __restrict__ go) {
    extern __shared__ float sm[];
    float* Qt = sm;
    float* Kt = sm + 64 * 132;
    float* Vs = Kt + 64 * 68;
    float* Ps = Vs + 64 * 68;

    const int tid = threadIdx.x;
    const int tx = tid & 15;
    const int ty = tid >> 4;
    const int b = blockIdx.y >> 4;
    const int h = blockIdx.y & 15;
    const int q0 = blockIdx.x << 7;

    const float* qb = gq + ((size_t)(b * 2048 + q0)) * 1024 + h * 64;
    const float* kb = gk + ((size_t)(b * 2048)) * 1024 + h * 64;
    const float* vb = gv + ((size_t)(b * 2048)) * 1024 + h * 64;

#pragma unroll
    for (int l = 0; l < 8; l++) {
        int r = (l << 4) + ty;
        int c = tx << 2;
        float4 v = *(const float4*)(qb + (size_t)r * 1024 + c);
        Qt[(c + 0) * 132 + r] = v.x * 0.125f;
        Qt[(c + 1) * 132 + r] = v.y * 0.125f;
        Qt[(c + 2) * 132 + r] = v.z * 0.125f;
        Qt[(c + 3) * 132 + r] = v.w * 0.125f;
    }

    float mrow[8], lrow[8];
    u64 ap[8][2];
#pragma unroll
    for (int i = 0; i < 8; i++) {
        mrow[i] = -1e30f; lrow[i] = 0.f;
        ap[i][0] = 0ull; ap[i][1] = 0ull;
    }
    __syncthreads();

    for (int s0 = 0; s0 < 2048; s0 += 64) {
        float4 kr[4], vr[4];
#pragma unroll
        for (int l = 0; l < 4; l++) {
            int r = (l << 4) + ty;
            int c = tx << 2;
            kr[l] = *(const float4*)(kb + (size_t)(s0 + r) * 1024 + c);
            vr[l] = *(const float4*)(vb + (size_t)(s0 + r) * 1024 + c);
        }
        __syncthreads();
#pragma unroll
        for (int l = 0; l < 4; l++) {
            int r = (l << 4) + ty;
            int c = tx << 2;
            Kt[(c + 0) * 68 + r] = kr[l].x;
            Kt[(c + 1) * 68 + r] = kr[l].y;
            Kt[(c + 2) * 68 + r] = kr[l].z;
            Kt[(c + 3) * 68 + r] = kr[l].w;
            *(float4*)&Vs[r * 68 + c] = vr[l];
        }
        __syncthreads();

        u64 sp[4][4];
#pragma unroll
        for (int qi = 0; qi < 4; qi++)
#pragma unroll
            for (int j = 0; j < 4; j++) sp[qi][j] = 0ull;
#pragma unroll 8
        for (int d = 0; d < 64; d++) {
            ulonglong2 qa = *(const ulonglong2*)&Qt[d * 132 + (ty << 3)];
            ulonglong2 qc = *(const ulonglong2*)&Qt[d * 132 + (ty << 3) + 4];
            float4 kf = *(const float4*)&Kt[d * 68 + (tx << 2)];
            u64 qp[4] = {qa.x, qa.y, qc.x, qc.y};
            u64 kd[4] = {dup2(kf.x), dup2(kf.y), dup2(kf.z), dup2(kf.w)};
#pragma unroll
            for (int qi = 0; qi < 4; qi++)
#pragma unroll
                for (int j = 0; j < 4; j++)
                    sp[qi][j] = ffma2(sp[qi][j], qp[qi], kd[j]);
        }

        float s[8][4];
#pragma unroll
        for (int qi = 0; qi < 4; qi++)
#pragma unroll
            for (int j = 0; j < 4; j++)
                unpack2(sp[qi][j], s[2 * qi][j], s[2 * qi + 1][j]);

#pragma unroll
        for (int i = 0; i < 8; i++) {
            float mx = fmaxf(fmaxf(s[i][0], s[i][1]), fmaxf(s[i][2], s[i][3]));
            mx = fmaxf(mx, __shfl_xor_sync(0xffffffffu, mx, 1));
            mx = fmaxf(mx, __shfl_xor_sync(0xffffffffu, mx, 2));
            mx = fmaxf(mx, __shfl_xor_sync(0xffffffffu, mx, 4));
            mx = fmaxf(mx, __shfl_xor_sync(0xffffffffu, mx, 8));
            float mn = fmaxf(mrow[i], mx);
            float alpha = __expf(mrow[i] - mn);
            mrow[i] = mn;
            float rs = 0.f;
#pragma unroll
            for (int j = 0; j < 4; j++) {
                s[i][j] = __expf(s[i][j] - mn);
                rs += s[i][j];
            }
            rs += __shfl_xor_sync(0xffffffffu, rs, 1);
            rs += __shfl_xor_sync(0xffffffffu, rs, 2);
            rs += __shfl_xor_sync(0xffffffffu, rs, 4);
            rs += __shfl_xor_sync(0xffffffffu, rs, 8);
            lrow[i] = lrow[i] * alpha + rs;
            u64 ad = dup2(alpha);
            ap[i][0] = fmul2(ap[i][0], ad);
            ap[i][1] = fmul2(ap[i][1], ad);
        }

#pragma unroll
        for (int i = 0; i < 8; i++)
            *(float4*)&Ps[((ty << 3) + i) * 68 + (tx << 2)] =
                make_float4(s[i][0], s[i][1], s[i][2], s[i][3]);
        __syncwarp();

#pragma unroll 2
        for (int j0 = 0; j0 < 64; j0 += 4) {
            float4 pr[8];
#pragma unroll
            for (int i = 0; i < 8; i++)
                pr[i] = *(const float4*)&Ps[((ty << 3) + i) * 68 + j0];
            u64 vp[4][2];
#pragma unroll
            for (int jj = 0; jj < 4; jj++) {
                ulonglong2 vv =
                    *(const ulonglong2*)&Vs[(j0 + jj) * 68 + (tx << 2)];
                vp[jj][0] = vv.x; vp[jj][1] = vv.y;
            }
#pragma unroll
            for (int i = 0; i < 8; i++) {
                const float* pf = &pr[i].x;
#pragma unroll
                for (int jj = 0; jj < 4; jj++) {
                    u64 pd = dup2(pf[jj]);
                    ap[i][0] = ffma2(ap[i][0], pd, vp[jj][0]);
                    ap[i][1] = ffma2(ap[i][1], pd, vp[jj][1]);
                }
            }
        }
    }

    float* ob = go + ((size_t)(b * 2048 + q0)) * 1024 + h * 64;
#pragma unroll
    for (int i = 0; i < 8; i++) {
        float inv = 1.0f / lrow[i];
        float o0, o1, o2, o3;
        unpack2(ap[i][0], o0, o1);
        unpack2(ap[i][1], o2, o3);
        *(float4*)(ob + (size_t)((ty << 3) + i) * 1024 + (tx << 2)) =
            make_float4(o0 * inv, o1 * inv, o2 * inv, o3 * inv);
    }
}

// ---------------------------------------------------------------------------
extern "C" void kernel_launch(void* const* d_in, const int* in_sizes, int n_in,
                              void* d_out, int out_size) {
    const float* Q  = (const float*)d_in[0];
    const float* K  = (const float*)d_in[1];
    const float* V  = (const float*)d_in[2];
    const float* Wq = (const float*)d_in[3];
    const float* Wk = (const float*)d_in[4];
    const float* Wv = (const float*)d_in[5];
    const float* Wo = (const float*)d_in[6];
    float* out = (float*)d_out;

    float *q, *k, *v, *a;
    __nv_bfloat16 *ah, *al, *wh, *wl;
    cudaGetSymbolAddress((void**)&q, g_q);
    cudaGetSymbolAddress((void**)&k, g_k);
    cudaGetSymbolAddress((void**)&v, g_v);
    cudaGetSymbolAddress((void**)&a, g_attn);
    cudaGetSymbolAddress((void**)&ah, g_ah);
    cudaGetSymbolAddress((void**)&al, g_al);
    cudaGetSymbolAddress((void**)&wh, g_wh);
    cudaGetSymbolAddress((void**)&wl, g_wl);

    const int SMEM_GEMM = 2 * 65536;
    const int SMEM_ATTN = (64 * 132 + 64 * 68 + 64 * 68 + 128 * 68) * 4;
    cudaFuncSetAttribute(gemm_mma, cudaFuncAttributeMaxDynamicSharedMemorySize,
                         SMEM_GEMM);
    cudaFuncSetAttribute(attn128, cudaFuncAttributeMaxDynamicSharedMemorySize,
                         SMEM_ATTN);

    const int N_ACT4 = 4096 * 1024 / 4, N_W4 = 1024 * 1024 / 4;
    dim3 gg(8, 32);

    cvt_bf16x2<<<(N_ACT4 + 255) / 256, 256>>>(Q, ah, al, N_ACT4);
    cvt_bf16x2<<<(N_W4 + 255) / 256, 256>>>(Wq, wh, wl, N_W4);
    gemm_mma<<<gg, 256, SMEM_GEMM>>>(ah, al, wh, wl, q);

    cvt_bf16x2<<<(N_ACT4 + 255) / 256, 256>>>(K, ah, al, N_ACT4);
    cvt_bf16x2<<<(N_W4 + 255) / 256, 256>>>(Wk, wh, wl, N_W4);
    gemm_mma<<<gg, 256, SMEM_GEMM>>>(ah, al, wh, wl, k);

    cvt_bf16x2<<<(N_ACT4 + 255) / 256, 256>>>(V, ah, al, N_ACT4);
    cvt_bf16x2<<<(N_W4 + 255) / 256, 256>>>(Wv, wh, wl, N_W4);
    gemm_mma<<<gg, 256, SMEM_GEMM>>>(ah, al, wh, wl, v);

    dim3 ag(16, 32);
    attn128<<<ag, 256, SMEM_ATTN>>>(q, k, v, a);

    cvt_bf16x2<<<(N_ACT4 + 255) / 256, 256>>>(a, ah, al, N_ACT4);
    cvt_bf16x2<<<(N_W4 + 255) / 256, 256>>>(Wo, wh, wl, N_W4);
    gemm_mma<<<gg, 256, SMEM_GEMM>>>(ah, al, wh, wl, out);
}

// round 5
// speedup vs baseline: 3.2693x; 1.9885x over previous
#include <cuda_runtime.h>
#include <cuda_bf16.h>
#include <cstdint>

typedef unsigned long long u64;

// Scratch (__device__ globals; no allocs allowed)
__device__ __nv_bfloat16 g_ah[4096 * 1024];   // act split / attn-out split
__device__ __nv_bfloat16 g_al[4096 * 1024];
__device__ __nv_bfloat16 g_wh[1024 * 1024];
__device__ __nv_bfloat16 g_wl[1024 * 1024];
__device__ __nv_bfloat16 g_qh[4096 * 1024];
__device__ __nv_bfloat16 g_ql[4096 * 1024];
__device__ __nv_bfloat16 g_kh[4096 * 1024];
__device__ __nv_bfloat16 g_kl[4096 * 1024];
__device__ __nv_bfloat16 g_vh[4096 * 1024];
__device__ __nv_bfloat16 g_vl[4096 * 1024];

// ---------------- helpers ----------------
__device__ __forceinline__ uint32_t smem_u32(const void* p) {
    uint32_t a;
    asm("{ .reg .u64 t; cvta.to.shared.u64 t, %1; cvt.u32.u64 %0, t; }"
        : "=r"(a) : "l"(p));
    return a;
}
__device__ __forceinline__ void cp_async16(uint32_t s, const void* g) {
    asm volatile("cp.async.cg.shared.global [%0], [%1], 16;" :: "r"(s), "l"(g));
}
__device__ __forceinline__ void cp_commit() {
    asm volatile("cp.async.commit_group;" ::: "memory");
}
template <int N>
__device__ __forceinline__ void cp_wait() {
    asm volatile("cp.async.wait_group %0;" :: "n"(N) : "memory");
}
__device__ __forceinline__ void ldsm4(uint32_t* r, uint32_t a) {
    asm volatile("ldmatrix.sync.aligned.m8n8.x4.shared.b16 {%0,%1,%2,%3}, [%4];"
                 : "=r"(r[0]), "=r"(r[1]), "=r"(r[2]), "=r"(r[3]) : "r"(a));
}
__device__ __forceinline__ void ldsm4t(uint32_t* r, uint32_t a) {
    asm volatile("ldmatrix.sync.aligned.m8n8.x4.trans.shared.b16 {%0,%1,%2,%3}, [%4];"
                 : "=r"(r[0]), "=r"(r[1]), "=r"(r[2]), "=r"(r[3]) : "r"(a));
}
__device__ __forceinline__ void mma_bf16(float* c, const uint32_t* a,
                                         const uint32_t* b) {
    asm volatile(
        "mma.sync.aligned.m16n8k16.row.col.f32.bf16.bf16.f32 "
        "{%0,%1,%2,%3}, {%4,%5,%6,%7}, {%8,%9}, {%0,%1,%2,%3};"
        : "+f"(c[0]), "+f"(c[1]), "+f"(c[2]), "+f"(c[3])
        : "r"(a[0]), "r"(a[1]), "r"(a[2]), "r"(a[3]), "r"(b[0]), "r"(b[1]));
}
// packed bf16x2 convert: d = {hi16: cvt(hs), lo16: cvt(ls)}
__device__ __forceinline__ uint32_t cvt2bf(float hs, float ls) {
    uint32_t r;
    asm("cvt.rn.bf16x2.f32 %0, %1, %2;" : "=r"(r) : "f"(hs), "f"(ls));
    return r;
}
// split pair (x = even col, y = odd col) -> hi pack + lo pack (exact hi+lo)
__device__ __forceinline__ void split_pair(float x, float y, uint32_t& hi,
                                           uint32_t& lo) {
    uint32_t u0 = __float_as_uint(x), u1 = __float_as_uint(y);
    hi = __byte_perm(u0, u1, 0x7632);
    float l0 = x - __uint_as_float(u0 & 0xffff0000u);
    float l1 = y - __uint_as_float(u1 & 0xffff0000u);
    lo = cvt2bf(l1, l0);
}

// ---------------------------------------------------------------------------
// fp32 -> (bf16 hi, bf16 lo) split conversion (inputs/weights)
// ---------------------------------------------------------------------------
__global__ void cvt_bf16x2(const float* __restrict__ x,
                           __nv_bfloat16* __restrict__ hi,
                           __nv_bfloat16* __restrict__ lo, int n4) {
    int i = blockIdx.x * blockDim.x + threadIdx.x;
    if (i >= n4) return;
    float4 v = ((const float4*)x)[i];
    uint32_t h0, l0, h1, l1;
    split_pair(v.x, v.y, h0, l0);
    split_pair(v.z, v.w, h1, l1);
    ((uint32_t*)hi)[2 * i] = h0;  ((uint32_t*)hi)[2 * i + 1] = h1;
    ((uint32_t*)lo)[2 * i] = l0;  ((uint32_t*)lo)[2 * i + 1] = l1;
}

// ---------------------------------------------------------------------------
// Tensor-core GEMM, 3-term bf16 split. Epilogue: fp32 C and/or split (Ch,Cl)
// with pre-scale (for Q: 0.125).
// ---------------------------------------------------------------------------
__global__ __launch_bounds__(256, 1)
void gemm_mma(const __nv_bfloat16* __restrict__ Ah,
              const __nv_bfloat16* __restrict__ Al,
              const __nv_bfloat16* __restrict__ Bh,
              const __nv_bfloat16* __restrict__ Bl,
              float* __restrict__ C,
              __nv_bfloat16* __restrict__ Ch,
              __nv_bfloat16* __restrict__ Cl, float scale) {
    extern __shared__ char smem[];
    const uint32_t sb = smem_u32(smem);

    const int tid = threadIdx.x;
    const int wid = tid >> 5, lid = tid & 31;
    const int m0 = blockIdx.y << 7, n0 = blockIdx.x << 7;
    const int wm = (wid & 3) << 5;
    const int wn = (wid >> 2) << 6;

    const int lrow = tid >> 3;
    const int lc8 = tid & 7;
    const uint32_t soff0 = (uint32_t)(lrow * 128 + ((lc8 ^ (lrow & 7)) << 4));
    const __nv_bfloat16* gsrc[4] = {Ah, Al, Bh, Bl};
    const int grb[4] = {m0, m0, n0, n0};

    const int grp = lid >> 3, win = lid & 7;
    int aswA[2]; uint32_t abase[2];
    const int gkA = grp >> 1;
#pragma unroll
    for (int i = 0; i < 2; i++) {
        int r = wm + i * 16 + ((grp & 1) << 3) + win;
        abase[i] = (uint32_t)(r * 128);
        aswA[i] = r & 7;
    }
    int aswB[4]; uint32_t bbase[4];
    const int gkB = grp & 1;
#pragma unroll
    for (int j = 0; j < 4; j++) {
        int r = wn + j * 16 + ((grp >> 1) << 3) + win;
        bbase[j] = (uint32_t)(r * 128);
        aswB[j] = r & 7;
    }

    float acc[2][8][4];
#pragma unroll
    for (int i = 0; i < 2; i++)
#pragma unroll
        for (int jt = 0; jt < 8; jt++)
#pragma unroll
            for (int e = 0; e < 4; e++) acc[i][jt][e] = 0.f;

    auto load_stage = [&](int st, int kb) {
        const uint32_t stb = sb + (uint32_t)st * 65536u;
#pragma unroll
        for (int t = 0; t < 4; t++) {
#pragma unroll
            for (int i = 0; i < 4; i++) {
                int row = lrow + (i << 5);
                const __nv_bfloat16* g =
                    gsrc[t] + (size_t)(grb[t] + row) * 1024 + kb * 64 + lc8 * 8;
                cp_async16(stb + (uint32_t)t * 16384u + soff0 + (uint32_t)(i << 12), g);
            }
        }
    };

    load_stage(0, 0);
    cp_commit();

    for (int kb = 0; kb < 16; kb++) {
        const int st = kb & 1;
        if (kb < 15) {
            load_stage(st ^ 1, kb + 1);
            cp_commit();
            cp_wait<1>();
        } else {
            cp_wait<0>();
        }
        __syncthreads();

        const uint32_t stb = sb + (uint32_t)st * 65536u;
#pragma unroll
        for (int t = 0; t < 4; t++) {
            uint32_t afh[2][4], afl[2][4];
#pragma unroll
            for (int i = 0; i < 2; i++) {
                uint32_t off = abase[i] + (uint32_t)((((2 * t + gkA) ^ aswA[i]) << 4));
                ldsm4(afh[i], stb + off);
                ldsm4(afl[i], stb + 16384u + off);
            }
            uint32_t bfh[4][4], bfl[4][4];
#pragma unroll
            for (int j = 0; j < 4; j++) {
                uint32_t off = bbase[j] + (uint32_t)((((2 * t + gkB) ^ aswB[j]) << 4));
                ldsm4(bfh[j], stb + 32768u + off);
                ldsm4(bfl[j], stb + 49152u + off);
            }
#pragma unroll
            for (int i = 0; i < 2; i++)
#pragma unroll
                for (int jt = 0; jt < 8; jt++) {
                    const int j = jt >> 1, hf = (jt & 1) << 1;
                    mma_bf16(acc[i][jt], afh[i], &bfh[j][hf]);
                    mma_bf16(acc[i][jt], afh[i], &bfl[j][hf]);
                    mma_bf16(acc[i][jt], afl[i], &bfh[j][hf]);
                }
        }
        __syncthreads();
    }

    const int eg = lid >> 2, ec = lid & 3;
#pragma unroll
    for (int i = 0; i < 2; i++) {
        const int row = m0 + wm + i * 16 + eg;
#pragma unroll
        for (int jt = 0; jt < 8; jt++) {
            const int col = n0 + wn + jt * 8 + ec * 2;
            if (C) {
                *(float2*)(C + (size_t)row * 1024 + col) =
                    make_float2(acc[i][jt][0], acc[i][jt][1]);
                *(float2*)(C + (size_t)(row + 8) * 1024 + col) =
                    make_float2(acc[i][jt][2], acc[i][jt][3]);
            }
            if (Ch) {
                uint32_t hp, lp;
                split_pair(acc[i][jt][0] * scale, acc[i][jt][1] * scale, hp, lp);
                *(uint32_t*)(Ch + (size_t)row * 1024 + col) = hp;
                *(uint32_t*)(Cl + (size_t)row * 1024 + col) = lp;
                split_pair(acc[i][jt][2] * scale, acc[i][jt][3] * scale, hp, lp);
                *(uint32_t*)(Ch + (size_t)(row + 8) * 1024 + col) = hp;
                *(uint32_t*)(Cl + (size_t)(row + 8) * 1024 + col) = lp;
            }
        }
    }
}

// ---------------------------------------------------------------------------
// Flash attention, mma.sync bf16 3-term split on both matmuls.
// CTA = 128 queries x one (b,h); 8 warps x 16 q-rows; key tiles of 128.
// Q pre-scaled by 1/8 at projection. Output written as (hi,lo) split.
// Smem: Qh,Ql (2x16KB) + 2 stages x {Kh,Kl,Vh,Vl} (2x64KB) = 160 KB.
// ---------------------------------------------------------------------------
__global__ __launch_bounds__(256, 1)
void attn_mma(const __nv_bfloat16* __restrict__ qh, const __nv_bfloat16* __restrict__ ql,
              const __nv_bfloat16* __restrict__ kh, const __nv_bfloat16* __restrict__ kl,
              const __nv_bfloat16* __restrict__ vh, const __nv_bfloat16* __restrict__ vl,
              __nv_bfloat16* __restrict__ oh, __nv_bfloat16* __restrict__ ol) {
    extern __shared__ char smem[];
    const uint32_t sb = smem_u32(smem);

    const int tid = threadIdx.x;
    const int wid = tid >> 5, lid = tid & 31;
    const int grp = lid >> 3, win = lid & 7;
    const int g = lid >> 2, cq = lid & 3;
    const int b = blockIdx.y >> 4, h = blockIdx.y & 15;
    const int q0 = blockIdx.x << 7;
    const int tokq = b * 2048 + q0;
    const int tokk = b * 2048;

    const int lrow = tid >> 3;
    const int lc8 = tid & 7;
    const uint32_t soff0 = (uint32_t)(lrow * 128 + ((lc8 ^ (lrow & 7)) << 4));

    // load Q tiles (hi at 0, lo at 16384)
#pragma unroll
    for (int i = 0; i < 4; i++) {
        int row = lrow + (i << 5);
        const __nv_bfloat16* gq = qh + (size_t)(tokq + row) * 1024 + h * 64 + lc8 * 8;
        const __nv_bfloat16* gl = ql + (size_t)(tokq + row) * 1024 + h * 64 + lc8 * 8;
        cp_async16(sb + soff0 + (uint32_t)(i << 12), gq);
        cp_async16(sb + 16384u + soff0 + (uint32_t)(i << 12), gl);
    }

    const __nv_bfloat16* kvsrc[4] = {kh, kl, vh, vl};
    auto load_kv = [&](int st, int kt) {
        const uint32_t stb = sb + 32768u + (uint32_t)st * 65536u;
#pragma unroll
        for (int t = 0; t < 4; t++) {
#pragma unroll
            for (int i = 0; i < 4; i++) {
                int row = lrow + (i << 5);
                const __nv_bfloat16* gp = kvsrc[t] +
                    (size_t)(tokk + kt * 128 + row) * 1024 + h * 64 + lc8 * 8;
                cp_async16(stb + (uint32_t)t * 16384u + soff0 + (uint32_t)(i << 12), gp);
            }
        }
    };

    load_kv(0, 0);
    cp_commit();

    uint32_t aqh[4][4], aql[4][4];
    float oacc[8][4];
    float mrow[2] = {-1e30f, -1e30f}, lsum[2] = {0.f, 0.f};
#pragma unroll
    for (int t = 0; t < 8; t++)
#pragma unroll
        for (int e = 0; e < 4; e++) oacc[t][e] = 0.f;

    for (int kt = 0; kt < 16; kt++) {
        const int st = kt & 1;
        if (kt < 15) {
            load_kv(st ^ 1, kt + 1);
            cp_commit();
            cp_wait<1>();
        } else {
            cp_wait<0>();
        }
        __syncthreads();

        if (kt == 0) {
            // Q A-fragments (GEMM-A pattern): row-half=grp&1, k-half=grp>>1
            const int qrow = (wid << 4) + ((grp & 1) << 3) + win;
#pragma unroll
            for (int kc = 0; kc < 4; kc++) {
                uint32_t off = (uint32_t)(qrow * 128) +
                               (uint32_t)((((kc << 1) + (grp >> 1)) ^ win) << 4);
                ldsm4(aqh[kc], sb + off);
                ldsm4(aql[kc], sb + 16384u + off);
            }
        }

        const uint32_t skh = sb + 32768u + (uint32_t)st * 65536u;
        const uint32_t skl = skh + 16384u;
        const uint32_t svh = skh + 32768u;
        const uint32_t svl = skh + 49152u;

        // ---- scores S[16][128] ----
        float sa[16][4];
#pragma unroll
        for (int t = 0; t < 16; t++)
#pragma unroll
            for (int e = 0; e < 4; e++) sa[t][e] = 0.f;

#pragma unroll
        for (int kc = 0; kc < 4; kc++) {
#pragma unroll
            for (int j2 = 0; j2 < 8; j2++) {
                const int krow = (j2 << 4) + ((grp >> 1) << 3) + win;
                uint32_t off = (uint32_t)(krow * 128) +
                               (uint32_t)((((kc << 1) + (grp & 1)) ^ win) << 4);
                uint32_t bh[4], bl[4];
                ldsm4(bh, skh + off);
                ldsm4(bl, skl + off);
                mma_bf16(sa[2 * j2], aqh[kc], bh);
                mma_bf16(sa[2 * j2], aqh[kc], bl);
                mma_bf16(sa[2 * j2], aql[kc], bh);
                mma_bf16(sa[2 * j2 + 1], aqh[kc], bh + 2);
                mma_bf16(sa[2 * j2 + 1], aqh[kc], bl + 2);
                mma_bf16(sa[2 * j2 + 1], aql[kc], bh + 2);
            }
        }

        // ---- online softmax (lane rows g and g+8; 4 lanes/row: shfl 1,2) ----
#pragma unroll
        for (int rr = 0; rr < 2; rr++) {
            const int e0 = rr << 1;
            float mx = -1e30f;
#pragma unroll
            for (int t = 0; t < 16; t++)
                mx = fmaxf(mx, fmaxf(sa[t][e0], sa[t][e0 + 1]));
            mx = fmaxf(mx, __shfl_xor_sync(0xffffffffu, mx, 1));
            mx = fmaxf(mx, __shfl_xor_sync(0xffffffffu, mx, 2));
            const float mn = fmaxf(mrow[rr], mx);
            const float alpha = __expf(mrow[rr] - mn);
            mrow[rr] = mn;
            float rs = 0.f;
#pragma unroll
            for (int t = 0; t < 16; t++) {
                float p0 = __expf(sa[t][e0] - mn);
                float p1 = __expf(sa[t][e0 + 1] - mn);
                sa[t][e0] = p0; sa[t][e0 + 1] = p1;
                rs += p0 + p1;
            }
            rs += __shfl_xor_sync(0xffffffffu, rs, 1);
            rs += __shfl_xor_sync(0xffffffffu, rs, 2);
            lsum[rr] = lsum[rr] * alpha + rs;
#pragma unroll
            for (int t = 0; t < 8; t++) {
                oacc[t][e0] *= alpha;
                oacc[t][e0 + 1] *= alpha;
            }
        }

        // ---- O += P @ V (P from regs; V via ldmatrix.trans) ----
#pragma unroll
        for (int pk = 0; pk < 8; pk++) {
            uint32_t aph[4], apl[4];
            split_pair(sa[2 * pk][0], sa[2 * pk][1], aph[0], apl[0]);
            split_pair(sa[2 * pk][2], sa[2 * pk][3], aph[1], apl[1]);
            split_pair(sa[2 * pk + 1][0], sa[2 * pk + 1][1], aph[2], apl[2]);
            split_pair(sa[2 * pk + 1][2], sa[2 * pk + 1][3], aph[3], apl[3]);

            const int vrow = (pk << 4) + ((grp & 1) << 3) + win;
#pragma unroll
            for (int dt = 0; dt < 4; dt++) {
                uint32_t off = (uint32_t)(vrow * 128) +
                               (uint32_t)((((dt << 1) + (grp >> 1)) ^ win) << 4);
                uint32_t vfh[4], vfl[4];
                ldsm4t(vfh, svh + off);
                ldsm4t(vfl, svl + off);
                mma_bf16(oacc[2 * dt], aph, vfh);
                mma_bf16(oacc[2 * dt], aph, vfl);
                mma_bf16(oacc[2 * dt], apl, vfh);
                mma_bf16(oacc[2 * dt + 1], aph, vfh + 2);
                mma_bf16(oacc[2 * dt + 1], aph, vfl + 2);
                mma_bf16(oacc[2 * dt + 1], apl, vfh + 2);
            }
        }
        __syncthreads();
    }

    // ---- epilogue: normalize, split, store ----
    const float inv0 = 1.0f / lsum[0];
    const float inv1 = 1.0f / lsum[1];
    const int row0 = tokq + (wid << 4) + g;
#pragma unroll
    for (int t = 0; t < 8; t++) {
        const int col = h * 64 + t * 8 + cq * 2;
        uint32_t hp, lp;
        split_pair(oacc[t][0] * inv0, oacc[t][1] * inv0, hp, lp);
        *(uint32_t*)(oh + (size_t)row0 * 1024 + col) = hp;
        *(uint32_t*)(ol + (size_t)row0 * 1024 + col) = lp;
        split_pair(oacc[t][2] * inv1, oacc[t][3] * inv1, hp, lp);
        *(uint32_t*)(oh + (size_t)(row0 + 8) * 1024 + col) = hp;
        *(uint32_t*)(ol + (size_t)(row0 + 8) * 1024 + col) = lp;
    }
}

// ---------------------------------------------------------------------------
extern "C" void kernel_launch(void* const* d_in, const int* in_sizes, int n_in,
                              void* d_out, int out_size) {
    const float* Q  = (const float*)d_in[0];
    const float* K  = (const float*)d_in[1];
    const float* V  = (const float*)d_in[2];
    const float* Wq = (const float*)d_in[3];
    const float* Wk = (const float*)d_in[4];
    const float* Wv = (const float*)d_in[5];
    const float* Wo = (const float*)d_in[6];
    float* out = (float*)d_out;

    __nv_bfloat16 *ah, *al, *wh, *wl, *qh, *ql, *kh, *kl, *vh, *vl;
    cudaGetSymbolAddress((void**)&ah, g_ah);
    cudaGetSymbolAddress((void**)&al, g_al);
    cudaGetSymbolAddress((void**)&wh, g_wh);
    cudaGetSymbolAddress((void**)&wl, g_wl);
    cudaGetSymbolAddress((void**)&qh, g_qh);
    cudaGetSymbolAddress((void**)&ql, g_ql);
    cudaGetSymbolAddress((void**)&kh, g_kh);
    cudaGetSymbolAddress((void**)&kl, g_kl);
    cudaGetSymbolAddress((void**)&vh, g_vh);
    cudaGetSymbolAddress((void**)&vl, g_vl);

    const int SMEM_GEMM = 2 * 65536;
    const int SMEM_ATTN = 163840;  // 32KB Q + 2*64KB K/V stages
    cudaFuncSetAttribute(gemm_mma, cudaFuncAttributeMaxDynamicSharedMemorySize,
                         SMEM_GEMM);
    cudaFuncSetAttribute(attn_mma, cudaFuncAttributeMaxDynamicSharedMemorySize,
                         SMEM_ATTN);

    const int N_ACT4 = 4096 * 1024 / 4, N_W4 = 1024 * 1024 / 4;
    dim3 gg(8, 32);

    cvt_bf16x2<<<(N_ACT4 + 255) / 256, 256>>>(Q, ah, al, N_ACT4);
    cvt_bf16x2<<<(N_W4 + 255) / 256, 256>>>(Wq, wh, wl, N_W4);
    gemm_mma<<<gg, 256, SMEM_GEMM>>>(ah, al, wh, wl, nullptr, qh, ql, 0.125f);

    cvt_bf16x2<<<(N_ACT4 + 255) / 256, 256>>>(K, ah, al, N_ACT4);
    cvt_bf16x2<<<(N_W4 + 255) / 256, 256>>>(Wk, wh, wl, N_W4);
    gemm_mma<<<gg, 256, SMEM_GEMM>>>(ah, al, wh, wl, nullptr, kh, kl, 1.0f);

    cvt_bf16x2<<<(N_ACT4 + 255) / 256, 256>>>(V, ah, al, N_ACT4);
    cvt_bf16x2<<<(N_W4 + 255) / 256, 256>>>(Wv, wh, wl, N_W4);
    gemm_mma<<<gg, 256, SMEM_GEMM>>>(ah, al, wh, wl, nullptr, vh, vl, 1.0f);

    dim3 ag(16, 32);
    attn_mma<<<ag, 256, SMEM_ATTN>>>(qh, ql, kh, kl, vh, vl, ah, al);

    cvt_bf16x2<<<(N_W4 + 255) / 256, 256>>>(Wo, wh, wl, N_W4);
    gemm_mma<<<gg, 256, SMEM_GEMM>>>(ah, al, wh, wl, out, nullptr, nullptr, 1.0f);
}